// round 13
// baseline (speedup 1.0000x reference)
#include <cuda_runtime.h>
#include <cstdint>
#include <math.h>

#define BDIM 256

static constexpr int Bb  = 64;
static constexpr int Hh  = 8;
static constexpr int Mm  = 1024;
static constexpr int Cc  = 128;
static constexpr int MID = 64;
static constexpr int TM    = 64;   // rows per tile
static constexpr int KST   = 144;  // k-tile row stride: 576B = 64 mod 128 -> conflict-free LDS.128
static constexpr int VST   = 128;
static constexpr int SPLIT = 4;
static constexpr int MCH   = Mm / SPLIT;   // 256
static constexpr int SLOT  = 256;  // per-chunk scratch: [0:64) pool, [64:192) v2, 192 m, 193 s, 194 cnt

__device__ float g_scratch[Bb * Hh * SPLIT * SLOT];
__device__ int   g_tick[Bb * Hh];          // zero-init; reset after use each launch

struct SmemLayout {
    float kt[2][TM][KST];             // 73728 B (double buffer)
    float vt[TM][VST];                // 32768 B (single buffer)
    int   idx[MCH];                   // 1024 B
    __align__(16) float lpt[TM][8];   // 2048 B  [row][warp]
    float v2c[8][Cc];                 // 4096 B
    float ms[8][2];
    int   cnt;
    int   last;
};

__device__ __forceinline__ uint32_t tf32b(float x){
    uint32_t r; asm("cvt.rna.tf32.f32 %0, %1;" : "=r"(r) : "f"(x)); return r;
}

__device__ __forceinline__ void mma8(float d[4],
    uint32_t a0, uint32_t a1, uint32_t a2, uint32_t a3,
    uint32_t b0, uint32_t b1)
{
    asm volatile(
        "mma.sync.aligned.m16n8k8.row.col.f32.tf32.tf32.f32 "
        "{%0,%1,%2,%3}, {%4,%5,%6,%7}, {%8,%9}, {%0,%1,%2,%3};"
        : "+f"(d[0]), "+f"(d[1]), "+f"(d[2]), "+f"(d[3])
        : "r"(a0), "r"(a1), "r"(a2), "r"(a3), "r"(b0), "r"(b1));
}

__device__ __forceinline__ void cp16(void* dst, const void* src){
    uint32_t d = (uint32_t)__cvta_generic_to_shared(dst);
    asm volatile("cp.async.cg.shared.global [%0], [%1], 16;" :: "r"(d), "l"(src));
}

// warp w loads rows w+8c (c=0..7); lane l loads 16B chunk l of the 512B row.
__device__ __forceinline__ void issue_k(SmemLayout* sm,
    const float* __restrict__ kf, int t, int st, int w, int l)
{
    #pragma unroll
    for (int c = 0; c < 8; c++){
        int lr  = w + 8 * c;
        int row = sm->idx[t * TM + lr];
        cp16((char*)&sm->kt[st][lr][0] + l * 16,
             (const char*)(kf + (size_t)row * Cc) + l * 16);
    }
}
__device__ __forceinline__ void issue_v(SmemLayout* sm,
    const float* __restrict__ vp, int t, int w, int l)
{
    #pragma unroll
    for (int c = 0; c < 8; c++){
        int lr  = w + 8 * c;
        int row = sm->idx[t * TM + lr];
        cp16((char*)&sm->vt[lr][0] + l * 16,
             (const char*)(vp + (size_t)row * Cc) + l * 16);
    }
}

__global__ __launch_bounds__(BDIM, 2)
void scatt_fused(
    const float* __restrict__ query,
    const float* __restrict__ key_feat,
    const int*   __restrict__ att_mask,
    const float* __restrict__ value1,
    const float* __restrict__ value2,
    const float* __restrict__ w_basic,
    const float* __restrict__ b_basic,
    const float* __restrict__ w_last,
    const float* __restrict__ w_last2,
    const float* __restrict__ b_last2,
    float*       __restrict__ out)
{
    extern __shared__ char smem_raw[];
    SmemLayout* sm = reinterpret_cast<SmemLayout*>(smem_raw);

    const int cid = blockIdx.x;          // 0..2047
    const int bh  = cid / SPLIT;
    const int s   = cid % SPLIT;
    const int b   = bh / Hh;
    const int h   = bh % Hh;
    const int tid = threadIdx.x;
    const int w   = tid >> 5;            // 0..7
    const int l   = tid & 31;
    const int g   = l >> 2;
    const int tig = l & 3;

    // ---- 1. Compact unmasked rows of this chunk (warp 0) ----
    if (w == 0){
        int base = 0;
        const int* mp = att_mask + b * Mm + s * MCH;
        for (int c = 0; c < MCH; c += 32){
            int mk = mp[c + l];
            unsigned bal = __ballot_sync(0xffffffffu, mk != 0);
            if (mk) sm->idx[base + __popc(bal & ((1u << l) - 1u))] = s * MCH + c + l;
            base += __popc(bal);
        }
        int mcp = (base + TM - 1) & ~(TM - 1);
        for (int j = base + l; j < mcp; j += 32) sm->idx[j] = s * MCH;  // pad rows
        if (l == 0) sm->cnt = base;
    }
    __syncthreads();
    const int Mc = sm->cnt;
    const int NT = (Mc + TM - 1) / TM;   // <= 4

    const float* kf  = key_feat + (size_t)bh * Mm * Cc;
    const float* v2p = value2   + (size_t)bh * Mm * Cc;

    // ---- 2. Prologue: K0, V0 in flight before any prologue math ----
    if (NT > 0) issue_k(sm, kf, 0, 0, w, l);
    asm volatile("cp.async.commit_group;");
    if (NT > 0) issue_v(sm, v2p, 0, w, l);
    asm volatile("cp.async.commit_group;");

    // ---- 3. W fragment (one n=8 tile per warp), q folded in, permuted k-order ----
    // mma step (K,j): k-slot tig -> phys col 16K+4tig+2j ; slot tig+4 -> +1.
    // A-side: raw f32 bits to tf32 HMMA (HW truncation); B-side RNA.
    uint32_t wb[16][2];
    const float* wbp = w_basic + (size_t)h * Cc * MID;
    const float* qp  = query + (size_t)bh * Cc;
    const int nb = 8 * w;
    #pragma unroll
    for (int K = 0; K < 8; K++){
        #pragma unroll
        for (int j = 0; j < 2; j++){
            int ca = 16 * K + 4 * tig + 2 * j;
            int cb = ca + 1;
            float qa = __ldg(qp + ca), qb = __ldg(qp + cb);
            wb[2*K+j][0] = tf32b(qa * wbp[ca * MID + nb + g]);
            wb[2*K+j][1] = tf32b(qb * wbp[cb * MID + nb + g]);
        }
    }
    const int c0 = nb + 2 * tig;
    float bb0 = b_basic[h * MID + c0], bb1 = b_basic[h * MID + c0 + 1];
    float wl0 = w_last[h * MID + c0],  wl1 = w_last[h * MID + c0 + 1];

    float pa0 = 0.f, pa1 = 0.f;          // pool partials (cols c0, c0+1)
    float mrun = -1.0e30f, srun = 0.f;   // flash softmax state
    float4 acc = make_float4(0.f, 0.f, 0.f, 0.f);

    // ---- 4. Fused main loop ----
    // group FIFO invariant at tile top: {V(t), K(t)} pending (K committed after V for t=0;
    // steady state pending = {V(t), K(t)} -> wait_group 1 completes through K(t).
    for (int t = 0; t < NT; t++){
        const int st = t & 1;
        asm volatile("cp.async.wait_group 1;");   // K(t) ready (V(t) may still fly)
        __syncthreads();

        if (t + 1 < NT) issue_k(sm, kf, t + 1, st ^ 1, w, l);
        asm volatile("cp.async.commit_group;");

        // MMA: 4 sub-tiles of 16 rows, n-tile = [nb, nb+8)
        #pragma unroll
        for (int sub = 0; sub < 4; sub++){
            float d[4] = {0.f, 0.f, 0.f, 0.f};
            const float* r0p = &sm->kt[st][16 * sub + g][4 * tig];
            const float* r1p = r0p + 8 * KST;
            #pragma unroll
            for (int K = 0; K < 8; K++){
                float4 x0 = *(const float4*)(r0p + 16 * K);
                float4 x1 = *(const float4*)(r1p + 16 * K);
                mma8(d, __float_as_uint(x0.x), __float_as_uint(x1.x),
                        __float_as_uint(x0.y), __float_as_uint(x1.y),
                        wb[2*K][0], wb[2*K][1]);
                mma8(d, __float_as_uint(x0.z), __float_as_uint(x1.z),
                        __float_as_uint(x0.w), __float_as_uint(x1.w),
                        wb[2*K+1][0], wb[2*K+1][1]);
            }
            int m0 = t * TM + 16 * sub;
            float vg  = (m0 + g)     < Mc ? 1.f : 0.f;
            float vg8 = (m0 + g + 8) < Mc ? 1.f : 0.f;
            float rA0 = fmaxf(d[0] + bb0, 0.f), rA1 = fmaxf(d[1] + bb1, 0.f);
            float rA2 = fmaxf(d[2] + bb0, 0.f), rA3 = fmaxf(d[3] + bb1, 0.f);
            pa0 += vg * rA0 + vg8 * rA2;
            pa1 += vg * rA1 + vg8 * rA3;
            float lg  = rA0 * wl0 + rA1 * wl1;   // row g partial over warp's 8 cols
            float lg8 = rA2 * wl0 + rA3 * wl1;   // row g+8
            lg  += __shfl_xor_sync(0xffffffffu, lg,  1);
            lg  += __shfl_xor_sync(0xffffffffu, lg,  2);
            lg8 += __shfl_xor_sync(0xffffffffu, lg8, 1);
            lg8 += __shfl_xor_sync(0xffffffffu, lg8, 2);
            if (tig == 0){
                sm->lpt[16 * sub + g][w]     = lg;
                sm->lpt[16 * sub + g + 8][w] = lg8;
            }
        }
        asm volatile("cp.async.wait_group 1;");   // V(t) ready (K(t+1) may still fly)
        __syncthreads();                          // logit partials visible

        // Online softmax + value2 accumulation (warp w owns rows 8r+w)
        float Lr[8];
        float newm = mrun;
        #pragma unroll
        for (int r = 0; r < 8; r++){
            int lr = 8 * r + w;
            float4 La = *(const float4*)&sm->lpt[lr][0];
            float4 Lb = *(const float4*)&sm->lpt[lr][4];
            float L = ((La.x + La.y) + (La.z + La.w))
                    + ((Lb.x + Lb.y) + (Lb.z + Lb.w));
            Lr[r] = (t * TM + lr) < Mc ? L : -1.0e30f;
            newm = fmaxf(newm, Lr[r]);
        }
        float sc = __expf(mrun - newm);
        srun *= sc; acc.x *= sc; acc.y *= sc; acc.z *= sc; acc.w *= sc;
        #pragma unroll
        for (int r = 0; r < 8; r++){
            int lr = 8 * r + w;
            float p = ((t * TM + lr) < Mc) ? __expf(Lr[r] - newm) : 0.f;
            srun += p;
            float4 v = *((const float4*)&sm->vt[lr][0] + l);
            acc.x += p * v.x; acc.y += p * v.y;
            acc.z += p * v.z; acc.w += p * v.w;
        }
        mrun = newm;

        __syncthreads();                          // vt fully consumed
        if (t + 1 < NT) issue_v(sm, v2p, t + 1, w, l);
        asm volatile("cp.async.commit_group;");
    }
    asm volatile("cp.async.wait_group 0;");

    // ---- 5. Pool reduce over g + write chunk partials to scratch ----
    pa0 += __shfl_xor_sync(0xffffffffu, pa0, 4);
    pa0 += __shfl_xor_sync(0xffffffffu, pa0, 8);
    pa0 += __shfl_xor_sync(0xffffffffu, pa0, 16);
    pa1 += __shfl_xor_sync(0xffffffffu, pa1, 4);
    pa1 += __shfl_xor_sync(0xffffffffu, pa1, 8);
    pa1 += __shfl_xor_sync(0xffffffffu, pa1, 16);
    float* gp = g_scratch + (size_t)cid * SLOT;
    if (l < 4){                      // g==0, tig==l -> cols nb+2l, nb+2l+1
        gp[nb + 2 * l]     = pa0;
        gp[nb + 2 * l + 1] = pa1;
    }
    *((float4*)&sm->v2c[w][0] + l) = acc;
    if (l == 0){ sm->ms[w][0] = mrun; sm->ms[w][1] = srun; }
    __syncthreads();

    {   // cross-warp flash merge -> one state per chunk
        float gm = -3.0e38f;
        #pragma unroll
        for (int ww = 0; ww < 8; ww++) gm = fmaxf(gm, sm->ms[ww][0]);
        float den = 0.f, num = 0.f;
        #pragma unroll
        for (int ww = 0; ww < 8; ww++){
            float cw = __expf(sm->ms[ww][0] - gm);
            den += cw * sm->ms[ww][1];
            if (tid < Cc) num += cw * sm->v2c[ww][tid];
        }
        if (tid < Cc) gp[64 + tid] = num;
        if (tid == 0){ gp[192] = gm; gp[193] = den; gp[194] = (float)Mc; }
    }

    // ---- 6. Last-chunk-done ticket; combiner finishes this bh ----
    __threadfence();
    __syncthreads();
    if (tid == 0)
        sm->last = (atomicAdd(&g_tick[bh], 1) == SPLIT - 1);
    __syncthreads();
    if (!sm->last) return;
    if (tid == 0) g_tick[bh] = 0;          // reset for next graph replay
    __threadfence();

    const float* base = g_scratch + (size_t)bh * SPLIT * SLOT;
    float* spool = &sm->lpt[0][0];         // reuse smem (>=64 floats)
    if (tid < MID){
        float p = 0.f;
        #pragma unroll
        for (int ss = 0; ss < SPLIT; ss++) p += base[ss * SLOT + tid];
        spool[tid] = p;
    }
    float gm2 = -3.0e38f, cntf = 0.f;
    #pragma unroll
    for (int ss = 0; ss < SPLIT; ss++){
        gm2  = fmaxf(gm2, base[ss * SLOT + 192]);
        cntf += base[ss * SLOT + 194];
    }
    float den2 = 0.f, num2 = 0.f;
    #pragma unroll
    for (int ss = 0; ss < SPLIT; ss++){
        float cw = __expf(base[ss * SLOT + 192] - gm2);
        den2 += cw * base[ss * SLOT + 193];
        if (tid < Cc) num2 += cw * base[ss * SLOT + 64 + tid];
    }
    __syncthreads();

    if (tid < Cc){
        float a = 0.f;
        const float* w2 = w_last2 + (size_t)h * MID * Cc + tid;
        #pragma unroll
        for (int o = 0; o < MID; o++) a += spool[o] * w2[o * Cc];
        float alpha = 1.f / (1.f + __expf(-(a / cntf + b_last2[h * Cc + tid])));

        out[(size_t)bh * Cc + tid] =
            value1[(size_t)bh * Cc + tid] * (num2 / den2) * alpha;
    }
}

extern "C" void kernel_launch(void* const* d_in, const int* in_sizes, int n_in,
                              void* d_out, int out_size)
{
    (void)in_sizes; (void)n_in; (void)out_size;
    const float* query    = (const float*)d_in[0];
    const float* key_feat = (const float*)d_in[1];
    const int*   att_mask = (const int*)  d_in[2];
    const float* value1   = (const float*)d_in[3];
    const float* value2   = (const float*)d_in[4];
    const float* w_basic  = (const float*)d_in[5];
    const float* b_basic  = (const float*)d_in[6];
    const float* w_last   = (const float*)d_in[7];
    // d_in[8] = b_last: uniform logit shift, cancels in softmax — unused.
    const float* w_last2  = (const float*)d_in[9];
    const float* b_last2  = (const float*)d_in[10];
    float* out = (float*)d_out;

    static_assert(sizeof(SmemLayout) <= 114 * 1024, "smem budget for 2 CTAs/SM");
    cudaFuncSetAttribute(scatt_fused,
                         cudaFuncAttributeMaxDynamicSharedMemorySize,
                         (int)sizeof(SmemLayout));
    scatt_fused<<<Bb * Hh * SPLIT, BDIM, sizeof(SmemLayout)>>>(
        query, key_feat, att_mask, value1, value2,
        w_basic, b_basic, w_last, w_last2, b_last2, out);
}

// round 14
// speedup vs baseline: 1.4448x; 1.4448x over previous
#include <cuda_runtime.h>
#include <cstdint>
#include <math.h>

#define BDIM 128

static constexpr int Bb  = 64;
static constexpr int Hh  = 8;
static constexpr int Mm  = 1024;
static constexpr int Cc  = 128;
static constexpr int MID = 64;
static constexpr int TM    = 32;   // rows per tile
static constexpr int NS    = 2;    // double buffer
static constexpr int KST   = 144;  // k-tile row stride: 576B = 64 mod 128 -> conflict-free LDS.128
static constexpr int VST   = 128;
static constexpr int SPLIT = 4;
static constexpr int MCH   = Mm / SPLIT;
static constexpr int SLOT  = 256;  // per-chunk scratch: [0:64) pool, [64:192) v2, 192 m, 193 s, 194 cnt

__device__ float g_scratch[Bb * Hh * SPLIT * SLOT];
__device__ int   g_tick[Bb * Hh];          // zero-init; reset after use each launch

struct SmemLayout {
    float kt[NS][TM][KST];
    float vt[NS][TM][VST];
    int   idx[MCH];
    __align__(16) float lpt[TM][4];   // [row][warp] -> one LDS.128 per row
    float v2c[4][Cc];
    float ms[4][2];
    int   cnt;
    int   last;
};

__device__ __forceinline__ uint32_t tf32b(float x){
    uint32_t r; asm("cvt.rna.tf32.f32 %0, %1;" : "=r"(r) : "f"(x)); return r;
}

__device__ __forceinline__ void mma8(float d[4],
    uint32_t a0, uint32_t a1, uint32_t a2, uint32_t a3,
    uint32_t b0, uint32_t b1)
{
    asm volatile(
        "mma.sync.aligned.m16n8k8.row.col.f32.tf32.tf32.f32 "
        "{%0,%1,%2,%3}, {%4,%5,%6,%7}, {%8,%9}, {%0,%1,%2,%3};"
        : "+f"(d[0]), "+f"(d[1]), "+f"(d[2]), "+f"(d[3])
        : "r"(a0), "r"(a1), "r"(a2), "r"(a3), "r"(b0), "r"(b1));
}

__device__ __forceinline__ void cp16(void* dst, const void* src){
    uint32_t d = (uint32_t)__cvta_generic_to_shared(dst);
    asm volatile("cp.async.cg.shared.global [%0], [%1], 16;" :: "r"(d), "l"(src));
}

__device__ __forceinline__ void issue_tile(SmemLayout* sm,
    const float* __restrict__ kf, const float* __restrict__ vp,
    int t, int st, int w, int l)
{
    #pragma unroll
    for (int c = 0; c < 8; c++){
        int lr  = 4 * c + w;
        int row = sm->idx[t * TM + lr];
        const char* ks = (const char*)(kf + (size_t)row * Cc) + l * 16;
        const char* vs = (const char*)(vp + (size_t)row * Cc) + l * 16;
        cp16((char*)&sm->kt[st][lr][0] + l * 16, ks);
        cp16((char*)&sm->vt[st][lr][0] + l * 16, vs);
    }
}

__global__ __launch_bounds__(BDIM, 3)
void scatt_fused(
    const float* __restrict__ query,
    const float* __restrict__ key_feat,
    const int*   __restrict__ att_mask,
    const float* __restrict__ value1,
    const float* __restrict__ value2,
    const float* __restrict__ w_basic,
    const float* __restrict__ b_basic,
    const float* __restrict__ w_last,
    const float* __restrict__ w_last2,
    const float* __restrict__ b_last2,
    float*       __restrict__ out)
{
    extern __shared__ char smem_raw[];
    SmemLayout* sm = reinterpret_cast<SmemLayout*>(smem_raw);

    const int cid = blockIdx.x;          // 0..2047
    const int bh  = cid / SPLIT;
    const int s   = cid % SPLIT;
    const int b   = bh / Hh;
    const int h   = bh % Hh;
    const int tid = threadIdx.x;
    const int w   = tid >> 5;
    const int l   = tid & 31;
    const int g   = l >> 2;
    const int tig = l & 3;

    // ---- 1. Compact unmasked rows of this chunk (warp 0) ----
    if (w == 0){
        int base = 0;
        const int* mp = att_mask + b * Mm + s * MCH;
        for (int c = 0; c < MCH; c += 32){
            int mk = mp[c + l];
            unsigned bal = __ballot_sync(0xffffffffu, mk != 0);
            if (mk) sm->idx[base + __popc(bal & ((1u << l) - 1u))] = s * MCH + c + l;
            base += __popc(bal);
        }
        int mcp = (base + TM - 1) & ~(TM - 1);
        if (base + l < mcp) sm->idx[base + l] = s * MCH;   // pad rows (masked out later)
        if (l == 0) sm->cnt = base;
    }
    __syncthreads();
    const int Mc = sm->cnt;
    const int NT = (Mc + TM - 1) / TM;

    const float* kf  = key_feat + (size_t)bh * Mm * Cc;
    const float* v2p = value2   + (size_t)bh * Mm * Cc;

    // ---- 2. Issue tile 0 ----
    if (0 < NT) issue_tile(sm, kf, v2p, 0, 0, w, l);
    asm volatile("cp.async.commit_group;");

    // ---- 3. W fragments, q folded in, PERMUTED k-order (RNA on B side only) ----
    // mma step (K,j): k-slot tig -> phys col 16K+4tig+2j ; slot tig+4 -> +1.
    // A-side reads 4 contiguous floats per (row,K): one LDS.128, raw bits to HMMA
    // (tf32 HW truncation == cvt.rz; B operand keeps RNA rounding).
    uint32_t wb0[16][2], wb1[16][2];
    const float* wbp = w_basic + (size_t)h * Cc * MID;
    const float* qp  = query + (size_t)bh * Cc;
    const int nb0 = 16 * w, nb1 = 16 * w + 8;
    #pragma unroll
    for (int K = 0; K < 8; K++){
        #pragma unroll
        for (int j = 0; j < 2; j++){
            int ca = 16 * K + 4 * tig + 2 * j;
            int cb = ca + 1;
            float qa = __ldg(qp + ca), qb = __ldg(qp + cb);
            wb0[2*K+j][0] = tf32b(qa * wbp[ca * MID + nb0 + g]);
            wb0[2*K+j][1] = tf32b(qb * wbp[cb * MID + nb0 + g]);
            wb1[2*K+j][0] = tf32b(qa * wbp[ca * MID + nb1 + g]);
            wb1[2*K+j][1] = tf32b(qb * wbp[cb * MID + nb1 + g]);
        }
    }
    const int c0 = nb0 + 2 * tig, c2 = nb1 + 2 * tig;
    float bb[4], wl[4];
    bb[0] = b_basic[h * MID + c0];  bb[1] = b_basic[h * MID + c0 + 1];
    bb[2] = b_basic[h * MID + c2];  bb[3] = b_basic[h * MID + c2 + 1];
    wl[0] = w_last[h * MID + c0];   wl[1] = w_last[h * MID + c0 + 1];
    wl[2] = w_last[h * MID + c2];   wl[3] = w_last[h * MID + c2 + 1];

    float pa[4] = {0.f, 0.f, 0.f, 0.f};
    float mrun = -1.0e30f, srun = 0.f;
    float4 acc = make_float4(0.f, 0.f, 0.f, 0.f);

    // ---- 4. Fused main loop ----
    for (int t = 0; t < NT; t++){
        const int st = t & 1;
        asm volatile("cp.async.wait_group 0;");
        __syncthreads();

        if (t + 1 < NT) issue_tile(sm, kf, v2p, t + 1, st ^ 1, w, l);
        asm volatile("cp.async.commit_group;");

        #pragma unroll
        for (int sub = 0; sub < 2; sub++){
            // 4 independent accumulator sets -> each touched once per K iter
            // (gap of 4 MMAs covers HMMA latency; merged below).
            float d0a[4] = {0.f,0.f,0.f,0.f};
            float d1a[4] = {0.f,0.f,0.f,0.f};
            float d0b[4] = {0.f,0.f,0.f,0.f};
            float d1b[4] = {0.f,0.f,0.f,0.f};
            const float* r0p = &sm->kt[st][16 * sub + g][4 * tig];
            const float* r1p = r0p + 8 * KST;
            #pragma unroll
            for (int K = 0; K < 8; K++){
                float4 x0 = *(const float4*)(r0p + 16 * K);
                float4 x1 = *(const float4*)(r1p + 16 * K);
                uint32_t a0 = __float_as_uint(x0.x), a1 = __float_as_uint(x1.x);
                uint32_t a2 = __float_as_uint(x0.y), a3 = __float_as_uint(x1.y);
                mma8(d0a, a0, a1, a2, a3, wb0[2*K][0], wb0[2*K][1]);
                mma8(d1a, a0, a1, a2, a3, wb1[2*K][0], wb1[2*K][1]);
                uint32_t a4 = __float_as_uint(x0.z), a5 = __float_as_uint(x1.z);
                uint32_t a6 = __float_as_uint(x0.w), a7 = __float_as_uint(x1.w);
                mma8(d0b, a4, a5, a6, a7, wb0[2*K+1][0], wb0[2*K+1][1]);
                mma8(d1b, a4, a5, a6, a7, wb1[2*K+1][0], wb1[2*K+1][1]);
            }
            int m0 = t * TM + 16 * sub;
            float vg  = (m0 + g)     < Mc ? 1.f : 0.f;
            float vg8 = (m0 + g + 8) < Mc ? 1.f : 0.f;
            float rA0 = fmaxf((d0a[0] + d0b[0]) + bb[0], 0.f);
            float rA1 = fmaxf((d0a[1] + d0b[1]) + bb[1], 0.f);
            float rA2 = fmaxf((d0a[2] + d0b[2]) + bb[0], 0.f);
            float rA3 = fmaxf((d0a[3] + d0b[3]) + bb[1], 0.f);
            float rB0 = fmaxf((d1a[0] + d1b[0]) + bb[2], 0.f);
            float rB1 = fmaxf((d1a[1] + d1b[1]) + bb[3], 0.f);
            float rB2 = fmaxf((d1a[2] + d1b[2]) + bb[2], 0.f);
            float rB3 = fmaxf((d1a[3] + d1b[3]) + bb[3], 0.f);
            pa[0] += vg * rA0 + vg8 * rA2;
            pa[1] += vg * rA1 + vg8 * rA3;
            pa[2] += vg * rB0 + vg8 * rB2;
            pa[3] += vg * rB1 + vg8 * rB3;
            float lg  = rA0 * wl[0] + rA1 * wl[1] + rB0 * wl[2] + rB1 * wl[3];
            float lg8 = rA2 * wl[0] + rA3 * wl[1] + rB2 * wl[2] + rB3 * wl[3];
            lg  += __shfl_xor_sync(0xffffffffu, lg,  1);
            lg  += __shfl_xor_sync(0xffffffffu, lg,  2);
            lg8 += __shfl_xor_sync(0xffffffffu, lg8, 1);
            lg8 += __shfl_xor_sync(0xffffffffu, lg8, 2);
            if (tig == 0){
                sm->lpt[16 * sub + g][w]     = lg;
                sm->lpt[16 * sub + g + 8][w] = lg8;
            }
        }
        __syncthreads();

        // Online softmax + value2 accumulation (warp w owns rows 4r+w)
        float Lr[8];
        float newm = mrun;
        #pragma unroll
        for (int r = 0; r < 8; r++){
            int lr = 4 * r + w;
            float4 Lv = *(const float4*)&sm->lpt[lr][0];   // one LDS.128 broadcast
            float L = (Lv.x + Lv.y) + (Lv.z + Lv.w);
            Lr[r] = (t * TM + lr) < Mc ? L : -1.0e30f;
            newm = fmaxf(newm, Lr[r]);
        }
        float sc = __expf(mrun - newm);
        srun *= sc; acc.x *= sc; acc.y *= sc; acc.z *= sc; acc.w *= sc;
        #pragma unroll
        for (int r = 0; r < 8; r++){
            int lr = 4 * r + w;
            float p = ((t * TM + lr) < Mc) ? __expf(Lr[r] - newm) : 0.f;
            srun += p;
            float4 v = *((const float4*)&sm->vt[st][lr][0] + l);
            acc.x += p * v.x; acc.y += p * v.y;
            acc.z += p * v.z; acc.w += p * v.w;
        }
        mrun = newm;
    }
    asm volatile("cp.async.wait_group 0;");

    // ---- 5. Reduce + write chunk partials to scratch ----
    #pragma unroll
    for (int c = 0; c < 4; c++){
        pa[c] += __shfl_xor_sync(0xffffffffu, pa[c], 4);
        pa[c] += __shfl_xor_sync(0xffffffffu, pa[c], 8);
        pa[c] += __shfl_xor_sync(0xffffffffu, pa[c], 16);
    }
    float* gp = g_scratch + (size_t)cid * SLOT;
    if (l < 4){
        gp[c0]     = pa[0];
        gp[c0 + 1] = pa[1];
        gp[c2]     = pa[2];
        gp[c2 + 1] = pa[3];
    }
    *((float4*)&sm->v2c[w][0] + l) = acc;
    if (l == 0){ sm->ms[w][0] = mrun; sm->ms[w][1] = srun; }
    __syncthreads();

    {   // cross-warp flash merge -> one state per chunk
        float gm = fmaxf(fmaxf(sm->ms[0][0], sm->ms[1][0]),
                         fmaxf(sm->ms[2][0], sm->ms[3][0]));
        float den = 0.f, num = 0.f;
        #pragma unroll
        for (int ww = 0; ww < 4; ww++){
            float cw = __expf(sm->ms[ww][0] - gm);
            den += cw * sm->ms[ww][1];
            num += cw * sm->v2c[ww][tid];
        }
        gp[64 + tid] = num;
        if (tid == 0){ gp[192] = gm; gp[193] = den; gp[194] = (float)Mc; }
    }

    // ---- 6. Last-chunk-done ticket; combiner finishes this bh ----
    __threadfence();
    __syncthreads();
    if (tid == 0)
        sm->last = (atomicAdd(&g_tick[bh], 1) == SPLIT - 1);
    __syncthreads();
    if (!sm->last) return;
    if (tid == 0) g_tick[bh] = 0;          // reset for next graph replay
    __threadfence();

    const float* base = g_scratch + (size_t)bh * SPLIT * SLOT;
    float* spool = &sm->lpt[0][0];         // reuse smem (>=64 floats)
    if (tid < MID){
        float p = 0.f;
        #pragma unroll
        for (int ss = 0; ss < SPLIT; ss++) p += base[ss * SLOT + tid];
        spool[tid] = p;
    }
    float gm2 = -3.0e38f, cntf = 0.f;
    #pragma unroll
    for (int ss = 0; ss < SPLIT; ss++){
        gm2  = fmaxf(gm2, base[ss * SLOT + 192]);
        cntf += base[ss * SLOT + 194];
    }
    float den2 = 0.f, num2 = 0.f;
    #pragma unroll
    for (int ss = 0; ss < SPLIT; ss++){
        float cw = __expf(base[ss * SLOT + 192] - gm2);
        den2 += cw * base[ss * SLOT + 193];
        num2 += cw * base[ss * SLOT + 64 + tid];
    }
    __syncthreads();

    float a = 0.f;
    const float* w2 = w_last2 + (size_t)h * MID * Cc + tid;
    #pragma unroll
    for (int o = 0; o < MID; o++) a += spool[o] * w2[o * Cc];
    float alpha = 1.f / (1.f + __expf(-(a / cntf + b_last2[h * Cc + tid])));

    out[(size_t)bh * Cc + tid] =
        value1[(size_t)bh * Cc + tid] * (num2 / den2) * alpha;
}

extern "C" void kernel_launch(void* const* d_in, const int* in_sizes, int n_in,
                              void* d_out, int out_size)
{
    (void)in_sizes; (void)n_in; (void)out_size;
    const float* query    = (const float*)d_in[0];
    const float* key_feat = (const float*)d_in[1];
    const int*   att_mask = (const int*)  d_in[2];
    const float* value1   = (const float*)d_in[3];
    const float* value2   = (const float*)d_in[4];
    const float* w_basic  = (const float*)d_in[5];
    const float* b_basic  = (const float*)d_in[6];
    const float* w_last   = (const float*)d_in[7];
    // d_in[8] = b_last: uniform logit shift, cancels in softmax — unused.
    const float* w_last2  = (const float*)d_in[9];
    const float* b_last2  = (const float*)d_in[10];
    float* out = (float*)d_out;

    static_assert(sizeof(SmemLayout) < 76 * 1024, "smem budget for 3 CTAs/SM");
    cudaFuncSetAttribute(scatt_fused,
                         cudaFuncAttributeMaxDynamicSharedMemorySize,
                         (int)sizeof(SmemLayout));
    scatt_fused<<<Bb * Hh * SPLIT, BDIM, sizeof(SmemLayout)>>>(
        query, key_feat, att_mask, value1, value2,
        w_basic, b_basic, w_last, w_last2, b_last2, out);
}